// round 9
// baseline (speedup 1.0000x reference)
#include <cuda_runtime.h>
#include <cuda_bf16.h>
#include <math.h>

#define BB   128
#define SS   400
#define HH   256
#define EE   128
#define VV   50000
#define PADV 250
#define VP   (VV + PADV)
#define NTILES_L 782          // ceil(50000/64)
#define TSTRIDE  784

// ---------------- static scratch ----------------
__device__ float g_gip[4][BB * 768];   // gi split-K partials
__device__ float g_ghp[8][BB * 768];   // gh split-K partials
__device__ float g_hid[BB * EE];
__device__ float g_logits[(size_t)BB * VV];
__device__ float g_tmax[BB * TSTRIDE];
__device__ float g_tsum[BB * TSTRIDE];
__device__ float g_pgen[BB];

// ---------------- math helpers (MUFU only, no div.rn) ----------------
__device__ __forceinline__ float sigm(float x)   { return __fdividef(1.f, 1.f + __expf(-x)); }
__device__ __forceinline__ float tanh_e(float x) { return 1.f - __fdividef(2.f, __expf(2.f * x) + 1.f); }

// packed fp32x2 FMA (Blackwell-only PTX; exact fp32 semantics)
__device__ __forceinline__ void fma2(unsigned long long& d, unsigned long long a, unsigned long long b) {
    asm("fma.rn.f32x2 %0, %1, %2, %3;" : "=l"(d) : "l"(a), "l"(b), "l"(d));
}
__device__ __forceinline__ float unpack_sum(unsigned long long v) {
    float lo, hi;
    asm("mov.b64 {%0,%1}, %2;" : "=f"(lo), "=f"(hi) : "l"(v));
    return lo + hi;
}

// ---------------- combined gi/gh split-K GEMM (one launch, no atomics) ----------------
// blockIdx.y in [0,12): y<4 -> gi chunk y (K=128), y>=4 -> gh chunk y-4 (K=256)
__global__ __launch_bounds__(256) void gates_gemm(
    const float* __restrict__ emb, const int* __restrict__ tok,
    const float* __restrict__ w_ih, const float* __restrict__ hprev,
    const float* __restrict__ w_hh)
{
    __shared__ float2 As[8][132];
    __shared__ float2 Ws[8][68];

    const int tid = threadIdx.x;
    const int tx = tid & 15;
    const int ty = tid >> 4;
    const int n0 = blockIdx.x * 64;
    const bool isGI = blockIdx.y < 4;
    const int  chunk = isGI ? blockIdx.y : (blockIdx.y - 4);
    const float* A = isGI ? emb : hprev;
    const float* W = isGI ? w_ih : w_hh;
    float* C = isGI ? g_gip[0] + (size_t)chunk * BB * 768
                    : g_ghp[0] + (size_t)chunk * BB * 768;
    const int K = isGI ? EE : HH;
    const int k0 = chunk * 32;
    const int kEnd = k0 + 32;

    unsigned long long acc[8][4];
#pragma unroll
    for (int i = 0; i < 8; i++)
#pragma unroll
        for (int j = 0; j < 4; j++) acc[i][j] = 0ULL;

    for (int kt = k0; kt < kEnd; kt += 16) {
        __syncthreads();
#pragma unroll
        for (int t = 0; t < 4; t++) {
            int lin = tid + t * 256;
            int m = lin >> 3, kp = lin & 7;
            int row = isGI ? tok[m] : m;
            As[kp][m] = *reinterpret_cast<const float2*>(A + (size_t)row * K + kt + 2 * kp);
        }
#pragma unroll
        for (int t = 0; t < 2; t++) {
            int lin = tid + t * 256;
            int nn = lin >> 3, kp = lin & 7;
            Ws[kp][nn] = *reinterpret_cast<const float2*>(W + (size_t)(n0 + nn) * K + kt + 2 * kp);
        }
        __syncthreads();

#pragma unroll
        for (int kp = 0; kp < 8; kp++) {
            unsigned long long a[8], w[4];
            const ulonglong2* ap = reinterpret_cast<const ulonglong2*>(&As[kp][ty * 8]);
            ulonglong2 q0 = ap[0], q1 = ap[1], q2 = ap[2], q3 = ap[3];
            a[0] = q0.x; a[1] = q0.y; a[2] = q1.x; a[3] = q1.y;
            a[4] = q2.x; a[5] = q2.y; a[6] = q3.x; a[7] = q3.y;
            const ulonglong2* wp = reinterpret_cast<const ulonglong2*>(&Ws[kp][tx * 4]);
            ulonglong2 r0 = wp[0], r1 = wp[1];
            w[0] = r0.x; w[1] = r0.y; w[2] = r1.x; w[3] = r1.y;
#pragma unroll
            for (int i = 0; i < 8; i++)
#pragma unroll
                for (int j = 0; j < 4; j++) fma2(acc[i][j], a[i], w[j]);
        }
    }

#pragma unroll
    for (int i = 0; i < 8; i++) {
        int m = ty * 8 + i;
#pragma unroll
        for (int j = 0; j < 4; j++) {
            int n = n0 + tx * 4 + j;
            C[(size_t)m * 768 + n] = unpack_sum(acc[i][j]);
        }
    }
}

// ---------------- mega-fused: GRU + scores + softmax + context + p_gen + outh GEMM ----------------
// one block per batch row, 1024 threads
__global__ __launch_bounds__(1024) void attn_fused(
    const float* __restrict__ enc, const float* __restrict__ emb,
    const int* __restrict__ tok, const float* __restrict__ hprev,
    const float* __restrict__ b_ih, const float* __restrict__ b_hh,
    const float* __restrict__ w_s, const float* __restrict__ attb,
    const float* __restrict__ w_h, const float* __restrict__ attv,
    const float* __restrict__ genw, const float* __restrict__ genb,
    const float* __restrict__ outhw, const float* __restrict__ outhb,
    float* __restrict__ out_h, float* __restrict__ out_at,
    float* __restrict__ out_pg)
{
    const int b = blockIdx.x, t = threadIdx.x;
    __shared__ float wsh[HH], wh[HH], av[HH], hnews[HH], ctx[HH];
    __shared__ float att[SS];
    __shared__ float red[1024];

    // ---- stage 0: sum gate partials + GRU for this row + smem param staging ----
    if (t < 256) {
        float gi0 = 0.f, gi1 = 0.f, gi2 = 0.f;
#pragma unroll
        for (int c = 0; c < 4; c++) {
            const float* p = g_gip[c] + b * 768;
            gi0 += p[t]; gi1 += p[256 + t]; gi2 += p[512 + t];
        }
        float gh0 = 0.f, gh1 = 0.f, gh2 = 0.f;
#pragma unroll
        for (int c = 0; c < 8; c++) {
            const float* p = g_ghp[c] + b * 768;
            gh0 += p[t]; gh1 += p[256 + t]; gh2 += p[512 + t];
        }
        float ir = gi0 + __ldg(b_ih + t);
        float iz = gi1 + __ldg(b_ih + 256 + t);
        float in_ = gi2 + __ldg(b_ih + 512 + t);
        float hr = gh0 + __ldg(b_hh + t);
        float hz = gh1 + __ldg(b_hh + 256 + t);
        float hn = gh2 + __ldg(b_hh + 512 + t);
        float r = sigm(ir + hr);
        float z = sigm(iz + hz);
        float n = tanh_e(in_ + r * hn);
        float hp = hprev[b * HH + t];
        float hnew = (1.f - z) * n + z * hp;
        hnews[t] = hnew;
        out_h[b * HH + t] = hnew;
        wsh[t] = fmaf(__ldg(w_s + t), hnew, __ldg(attb));
    } else if (t < 512) {
        wh[t - 256] = __ldg(w_h + (t - 256));
    } else if (t < 768) {
        av[t - 512] = __ldg(attv + (t - 512));
    }
    __syncthreads();

    // ---- stage 1: scores (32 warps over 400 rows) ----
    {
        const int wid = t >> 5, lane = t & 31;
        const int h0 = lane * 8;
        float4 w0 = *reinterpret_cast<const float4*>(wh  + h0);
        float4 w1 = *reinterpret_cast<const float4*>(wh  + h0 + 4);
        float4 s0 = *reinterpret_cast<const float4*>(wsh + h0);
        float4 s1 = *reinterpret_cast<const float4*>(wsh + h0 + 4);
        float4 v0 = *reinterpret_cast<const float4*>(av  + h0);
        float4 v1 = *reinterpret_cast<const float4*>(av  + h0 + 4);
        for (int s = wid; s < SS; s += 32) {
            const float4* e = reinterpret_cast<const float4*>(enc + ((size_t)b * SS + s) * HH + h0);
            float4 e0 = e[0], e1 = e[1];
            float sum;
            sum  = v0.x * tanh_e(fmaf(w0.x, e0.x, s0.x));
            sum += v0.y * tanh_e(fmaf(w0.y, e0.y, s0.y));
            sum += v0.z * tanh_e(fmaf(w0.z, e0.z, s0.z));
            sum += v0.w * tanh_e(fmaf(w0.w, e0.w, s0.w));
            sum += v1.x * tanh_e(fmaf(w1.x, e1.x, s1.x));
            sum += v1.y * tanh_e(fmaf(w1.y, e1.y, s1.y));
            sum += v1.z * tanh_e(fmaf(w1.z, e1.z, s1.z));
            sum += v1.w * tanh_e(fmaf(w1.w, e1.w, s1.w));
#pragma unroll
            for (int o = 16; o; o >>= 1) sum += __shfl_xor_sync(0xffffffffu, sum, o);
            if (lane == 0) att[s] = sum;
        }
    }
    __syncthreads();

    // ---- stage 2: softmax over S=400 ----
    float v = (t < SS) ? att[t] : -INFINITY;
    red[t] = v; __syncthreads();
#pragma unroll
    for (int o = 512; o; o >>= 1) { if (t < o) red[t] = fmaxf(red[t], red[t + o]); __syncthreads(); }
    float mx = red[0]; __syncthreads();
    float ev = (t < SS) ? __expf(v - mx) : 0.f;
    red[t] = ev; __syncthreads();
#pragma unroll
    for (int o = 512; o; o >>= 1) { if (t < o) red[t] += red[t + o]; __syncthreads(); }
    float inv = __fdividef(1.f, red[0]); __syncthreads();
    if (t < SS) {
        float a = ev * inv;
        att[t] = a;
        out_at[b * SS + t] = a;
    }
    __syncthreads();

    // ---- stage 3: context (4-way S split per h) ----
    {
        int h = t & 255;
        int part = t >> 8;
        int sBeg = part * 100;
        const float* e = enc + (size_t)b * SS * HH + (size_t)sBeg * HH + h;
        float c = 0.f;
#pragma unroll 10
        for (int s = 0; s < 100; s++) c = fmaf(att[sBeg + s], e[(size_t)s * HH], c);
        red[t] = c;
    }
    __syncthreads();
    if (t < 512) red[t] += red[t + 512];
    __syncthreads();
    if (t < 256) ctx[t] = red[t] + red[t + 256];
    __syncthreads();

    // ---- stage 4: p_gen ----
    float pv = 0.f;
    if (t < 256)      pv = hnews[t] * __ldg(genw + t);
    else if (t < 512) pv = ctx[t - 256] * __ldg(genw + t);
    else if (t < 640) pv = emb[(size_t)tok[b] * EE + (t - 512)] * __ldg(genw + t);
    red[t] = pv; __syncthreads();
#pragma unroll
    for (int o = 512; o; o >>= 1) { if (t < o) red[t] += red[t + o]; __syncthreads(); }
    if (t == 0) {
        float p = sigm(red[0] + __ldg(genb));
        out_pg[b] = p;
        g_pgen[b] = p;
    }

    // ---- stage 5: hid[b][n] = outh_b[n] + dot(outh_w[n,:], [hnews|ctx]) ----
    {
        int n = t >> 3;          // 0..127
        int kpart = t & 7;       // 0..7, each 64 k's
        const float* dcsrc = (kpart < 4) ? (hnews + kpart * 64) : (ctx + (kpart - 4) * 64);
        const float* wrow = outhw + (size_t)n * 512 + kpart * 64;
        float s = 0.f;
#pragma unroll
        for (int i = 0; i < 64; i += 4) {
            float4 wv = *reinterpret_cast<const float4*>(wrow + i);
            s += wv.x * dcsrc[i]     + wv.y * dcsrc[i + 1]
               + wv.z * dcsrc[i + 2] + wv.w * dcsrc[i + 3];
        }
#pragma unroll
        for (int o = 4; o; o >>= 1) s += __shfl_xor_sync(0xffffffffu, s, o);
        if (kpart == 0) g_hid[b * EE + n] = s + __ldg(outhb + n);
    }
}

// ---------------- logits GEMM: BM=128, BN=64, 128 thr, 8x8 microtile (crossbar-balanced) ----------------
__global__ __launch_bounds__(128) void logits_kernel(
    const float* __restrict__ A, const float* __restrict__ W,
    const float* __restrict__ bias, float* __restrict__ C)
{
    __shared__ float2 As[8][132];
    __shared__ float2 Ws[8][68];

    const int tid = threadIdx.x;
    const int tx = tid & 7;     // n group (8 x 8n = 64)
    const int ty = tid >> 3;    // m group (16 x 8m = 128)
    const int n0 = blockIdx.x * 64;

    unsigned long long acc[8][8];
#pragma unroll
    for (int i = 0; i < 8; i++)
#pragma unroll
        for (int j = 0; j < 8; j++) acc[i][j] = 0ULL;

    for (int kt = 0; kt < EE; kt += 16) {
        __syncthreads();
        // A tile: 128 m x 8 kp float2 = 1024, 8 per thread
#pragma unroll
        for (int t = 0; t < 8; t++) {
            int lin = tid + t * 128;
            int m = lin >> 3, kp = lin & 7;
            As[kp][m] = *reinterpret_cast<const float2*>(A + (size_t)m * EE + kt + 2 * kp);
        }
        // W tile: 64 n x 8 kp float2 = 512, 4 per thread
#pragma unroll
        for (int t = 0; t < 4; t++) {
            int lin = tid + t * 128;
            int nn = lin >> 3, kp = lin & 7;
            int row = n0 + nn;
            if (row >= VV) row = VV - 1;
            Ws[kp][nn] = *reinterpret_cast<const float2*>(W + (size_t)row * EE + kt + 2 * kp);
        }
        __syncthreads();

#pragma unroll
        for (int kp = 0; kp < 8; kp++) {
            unsigned long long a[8], w[8];
            const ulonglong2* ap = reinterpret_cast<const ulonglong2*>(&As[kp][ty * 8]);
            ulonglong2 q0 = ap[0], q1 = ap[1], q2 = ap[2], q3 = ap[3];
            a[0] = q0.x; a[1] = q0.y; a[2] = q1.x; a[3] = q1.y;
            a[4] = q2.x; a[5] = q2.y; a[6] = q3.x; a[7] = q3.y;
            const ulonglong2* wp = reinterpret_cast<const ulonglong2*>(&Ws[kp][tx * 8]);
            ulonglong2 r0 = wp[0], r1 = wp[1], r2 = wp[2], r3 = wp[3];
            w[0] = r0.x; w[1] = r0.y; w[2] = r1.x; w[3] = r1.y;
            w[4] = r2.x; w[5] = r2.y; w[6] = r3.x; w[7] = r3.y;
#pragma unroll
            for (int i = 0; i < 8; i++)
#pragma unroll
                for (int j = 0; j < 8; j++) fma2(acc[i][j], a[i], w[j]);
        }
    }

    // epilogue: bias add, store logits, per-(row,tile) max + sumexp partials
#pragma unroll
    for (int i = 0; i < 8; i++) {
        int m = ty * 8 + i;
        float vls[8];
        float mloc = -INFINITY;
#pragma unroll
        for (int j = 0; j < 8; j++) {
            int n = n0 + tx * 8 + j;
            bool valid = n < VV;
            int nc = valid ? n : VV - 1;
            float c = unpack_sum(acc[i][j]) + __ldg(bias + nc);
            if (valid) {
                C[(size_t)m * VV + n] = c;
                mloc = fmaxf(mloc, c);
                vls[j] = c;
            } else {
                vls[j] = -INFINITY;
            }
        }
        // reduce across the 8 tx lanes (xor 1,2,4 stays inside the 8-lane group)
#pragma unroll
        for (int o = 4; o; o >>= 1) mloc = fmaxf(mloc, __shfl_xor_sync(0xffffffffu, mloc, o));
        float s = 0.f;
#pragma unroll
        for (int j = 0; j < 8; j++) if (vls[j] > -INFINITY) s += __expf(vls[j] - mloc);
#pragma unroll
        for (int o = 4; o; o >>= 1) s += __shfl_xor_sync(0xffffffffu, s, o);
        if (tx == 0) {
            g_tmax[m * TSTRIDE + blockIdx.x] = mloc;
            g_tsum[m * TSTRIDE + blockIdx.x] = s;
        }
    }
}

// ---------------- finalize (fused merge) ----------------
__global__ __launch_bounds__(256) void finalize_kernel(float* __restrict__ out_pv, float* __restrict__ out_pf)
{
    int b = blockIdx.y, t = threadIdx.x;
    __shared__ float red[256];

    // in-block merge of 782 tile partials
    float mx = -INFINITY;
    for (int i = t; i < NTILES_L; i += 256) mx = fmaxf(mx, g_tmax[b * TSTRIDE + i]);
    red[t] = mx; __syncthreads();
#pragma unroll
    for (int o = 128; o; o >>= 1) { if (t < o) red[t] = fmaxf(red[t], red[t + o]); __syncthreads(); }
    mx = red[0]; __syncthreads();
    float s = 0.f;
    for (int i = t; i < NTILES_L; i += 256)
        s += g_tsum[b * TSTRIDE + i] * __expf(g_tmax[b * TSTRIDE + i] - mx);
    red[t] = s; __syncthreads();
#pragma unroll
    for (int o = 128; o; o >>= 1) { if (t < o) red[t] += red[t + o]; __syncthreads(); }
    float inv = __fdividef(1.f, red[0]);
    float pg = g_pgen[b];

    int start = blockIdx.x * 2000;
    const float* lg = g_logits + (size_t)b * VV + start;
    float* pv = out_pv + (size_t)b * VV + start;
    float* pf = out_pf + (size_t)b * VP + start;
    for (int i = t; i < 2000; i += 256) {
        float e = __expf(lg[i] - mx) * inv;
        pv[i] = e;
        pf[i] = e * pg;
    }
    if (blockIdx.x == 0 && t < PADV) out_pf[(size_t)b * VP + VV + t] = 0.f;
}

// ---------------- copy-mechanism scatter ----------------
__global__ void scatter_kernel(const int* __restrict__ fiv, const float* __restrict__ att,
                               float* __restrict__ out_pf)
{
    int b = blockIdx.x, s = threadIdx.x;
    if (s < SS) {
        float w = (1.f - g_pgen[b]) * att[b * SS + s];
        atomicAdd(&out_pf[(size_t)b * VP + fiv[b * SS + s]], w);
    }
}

// ---------------- launch ----------------
extern "C" void kernel_launch(void* const* d_in, const int* in_sizes, int n_in,
                              void* d_out, int out_size)
{
    const int*   tok   = (const int*)d_in[0];
    const float* hprev = (const float*)d_in[1];
    const float* enc   = (const float*)d_in[2];
    const int*   fiv   = (const int*)d_in[3];
    const float* emb   = (const float*)d_in[4];
    const float* w_ih  = (const float*)d_in[5];
    const float* w_hh  = (const float*)d_in[6];
    const float* b_ih  = (const float*)d_in[7];
    const float* b_hh  = (const float*)d_in[8];
    const float* w_h   = (const float*)d_in[9];
    const float* w_s   = (const float*)d_in[10];
    const float* attb  = (const float*)d_in[11];
    const float* attv  = (const float*)d_in[12];
    const float* genw  = (const float*)d_in[13];
    const float* genb  = (const float*)d_in[14];
    const float* outhw = (const float*)d_in[15];
    const float* outhb = (const float*)d_in[16];
    const float* outvw = (const float*)d_in[17];
    const float* outvb = (const float*)d_in[18];

    float* out    = (float*)d_out;
    float* out_h  = out;
    float* out_pf = out + 32768;
    float* out_pg = out + 6464768;
    float* out_pv = out + 6464896;
    float* out_at = out + 12864896;

    float *p_hid, *p_logits;
    cudaGetSymbolAddress((void**)&p_hid,    g_hid);
    cudaGetSymbolAddress((void**)&p_logits, g_logits);

    gates_gemm<<<dim3(12, 12), 256>>>(emb, tok, w_ih, hprev, w_hh);

    attn_fused<<<128, 1024>>>(enc, emb, tok, hprev, b_ih, b_hh, w_s, attb,
                              w_h, attv, genw, genb, outhw, outhb,
                              out_h, out_at, out_pg);

    logits_kernel<<<NTILES_L, 128>>>(p_hid, outvw, outvb, p_logits);

    finalize_kernel<<<dim3(25, 128), 256>>>(out_pv, out_pf);
    scatter_kernel<<<128, 512>>>(fiv, out_at, out_pf);
}

// round 10
// speedup vs baseline: 1.2085x; 1.2085x over previous
#include <cuda_runtime.h>
#include <cuda_bf16.h>
#include <math.h>

#define BB   128
#define SS   400
#define HH   256
#define EE   128
#define VV   50000
#define PADV 250
#define VP   (VV + PADV)
#define NTILES_L 782          // ceil(50000/64)
#define TSTRIDE  784

// ---------------- static scratch ----------------
__device__ float g_gip[4][BB * 768];   // gi split-K partials
__device__ float g_ghp[8][BB * 768];   // gh split-K partials
__device__ float g_hid[BB * EE];
__device__ float g_expv[(size_t)BB * VV];   // exp(logit - tile_max)
__device__ float g_tmax[BB * TSTRIDE];
__device__ float g_tsum[BB * TSTRIDE];
__device__ float g_rowmax[BB];
__device__ float g_rowinv[BB];
__device__ float g_pgen[BB];

// ---------------- math helpers (MUFU only, no div.rn) ----------------
__device__ __forceinline__ float sigm(float x)   { return __fdividef(1.f, 1.f + __expf(-x)); }
__device__ __forceinline__ float tanh_e(float x) { return 1.f - __fdividef(2.f, __expf(2.f * x) + 1.f); }

// packed fp32x2 FMA (Blackwell-only PTX; exact fp32 semantics)
__device__ __forceinline__ void fma2(unsigned long long& d, unsigned long long a, unsigned long long b) {
    asm("fma.rn.f32x2 %0, %1, %2, %3;" : "=l"(d) : "l"(a), "l"(b), "l"(d));
}
__device__ __forceinline__ float unpack_sum(unsigned long long v) {
    float lo, hi;
    asm("mov.b64 {%0,%1}, %2;" : "=f"(lo), "=f"(hi) : "l"(v));
    return lo + hi;
}

// ---------------- combined gi/gh split-K GEMM (one launch, no atomics) ----------------
__global__ __launch_bounds__(256) void gates_gemm(
    const float* __restrict__ emb, const int* __restrict__ tok,
    const float* __restrict__ w_ih, const float* __restrict__ hprev,
    const float* __restrict__ w_hh)
{
    __shared__ float2 As[8][132];
    __shared__ float2 Ws[8][68];

    const int tid = threadIdx.x;
    const int tx = tid & 15;
    const int ty = tid >> 4;
    const int n0 = blockIdx.x * 64;
    const bool isGI = blockIdx.y < 4;
    const int  chunk = isGI ? blockIdx.y : (blockIdx.y - 4);
    const float* A = isGI ? emb : hprev;
    const float* W = isGI ? w_ih : w_hh;
    float* C = isGI ? g_gip[0] + (size_t)chunk * BB * 768
                    : g_ghp[0] + (size_t)chunk * BB * 768;
    const int K = isGI ? EE : HH;
    const int k0 = chunk * 32;
    const int kEnd = k0 + 32;

    unsigned long long acc[8][4];
#pragma unroll
    for (int i = 0; i < 8; i++)
#pragma unroll
        for (int j = 0; j < 4; j++) acc[i][j] = 0ULL;

    for (int kt = k0; kt < kEnd; kt += 16) {
        __syncthreads();
#pragma unroll
        for (int t = 0; t < 4; t++) {
            int lin = tid + t * 256;
            int m = lin >> 3, kp = lin & 7;
            int row = isGI ? tok[m] : m;
            As[kp][m] = *reinterpret_cast<const float2*>(A + (size_t)row * K + kt + 2 * kp);
        }
#pragma unroll
        for (int t = 0; t < 2; t++) {
            int lin = tid + t * 256;
            int nn = lin >> 3, kp = lin & 7;
            Ws[kp][nn] = *reinterpret_cast<const float2*>(W + (size_t)(n0 + nn) * K + kt + 2 * kp);
        }
        __syncthreads();

#pragma unroll
        for (int kp = 0; kp < 8; kp++) {
            unsigned long long a[8], w[4];
            const ulonglong2* ap = reinterpret_cast<const ulonglong2*>(&As[kp][ty * 8]);
            ulonglong2 q0 = ap[0], q1 = ap[1], q2 = ap[2], q3 = ap[3];
            a[0] = q0.x; a[1] = q0.y; a[2] = q1.x; a[3] = q1.y;
            a[4] = q2.x; a[5] = q2.y; a[6] = q3.x; a[7] = q3.y;
            const ulonglong2* wp = reinterpret_cast<const ulonglong2*>(&Ws[kp][tx * 4]);
            ulonglong2 r0 = wp[0], r1 = wp[1];
            w[0] = r0.x; w[1] = r0.y; w[2] = r1.x; w[3] = r1.y;
#pragma unroll
            for (int i = 0; i < 8; i++)
#pragma unroll
                for (int j = 0; j < 4; j++) fma2(acc[i][j], a[i], w[j]);
        }
    }

#pragma unroll
    for (int i = 0; i < 8; i++) {
        int m = ty * 8 + i;
#pragma unroll
        for (int j = 0; j < 4; j++) {
            int n = n0 + tx * 4 + j;
            C[(size_t)m * 768 + n] = unpack_sum(acc[i][j]);
        }
    }
}

// ---------------- mega-fused: GRU + scores + softmax + context + p_gen + outh GEMM ----------------
__global__ __launch_bounds__(1024) void attn_fused(
    const float* __restrict__ enc, const float* __restrict__ emb,
    const int* __restrict__ tok, const float* __restrict__ hprev,
    const float* __restrict__ b_ih, const float* __restrict__ b_hh,
    const float* __restrict__ w_s, const float* __restrict__ attb,
    const float* __restrict__ w_h, const float* __restrict__ attv,
    const float* __restrict__ genw, const float* __restrict__ genb,
    const float* __restrict__ outhw, const float* __restrict__ outhb,
    float* __restrict__ out_h, float* __restrict__ out_at,
    float* __restrict__ out_pg)
{
    const int b = blockIdx.x, t = threadIdx.x;
    __shared__ float wsh[HH], wh[HH], av[HH], hnews[HH], ctx[HH];
    __shared__ float att[SS];
    __shared__ float red[1024];

    // ---- stage 0: sum gate partials + GRU + smem param staging ----
    if (t < 256) {
        float gi0 = 0.f, gi1 = 0.f, gi2 = 0.f;
#pragma unroll
        for (int c = 0; c < 4; c++) {
            const float* p = g_gip[c] + b * 768;
            gi0 += p[t]; gi1 += p[256 + t]; gi2 += p[512 + t];
        }
        float gh0 = 0.f, gh1 = 0.f, gh2 = 0.f;
#pragma unroll
        for (int c = 0; c < 8; c++) {
            const float* p = g_ghp[c] + b * 768;
            gh0 += p[t]; gh1 += p[256 + t]; gh2 += p[512 + t];
        }
        float ir = gi0 + __ldg(b_ih + t);
        float iz = gi1 + __ldg(b_ih + 256 + t);
        float in_ = gi2 + __ldg(b_ih + 512 + t);
        float hr = gh0 + __ldg(b_hh + t);
        float hz = gh1 + __ldg(b_hh + 256 + t);
        float hn = gh2 + __ldg(b_hh + 512 + t);
        float r = sigm(ir + hr);
        float z = sigm(iz + hz);
        float n = tanh_e(in_ + r * hn);
        float hp = hprev[b * HH + t];
        float hnew = (1.f - z) * n + z * hp;
        hnews[t] = hnew;
        out_h[b * HH + t] = hnew;
        wsh[t] = fmaf(__ldg(w_s + t), hnew, __ldg(attb));
    } else if (t < 512) {
        wh[t - 256] = __ldg(w_h + (t - 256));
    } else if (t < 768) {
        av[t - 512] = __ldg(attv + (t - 512));
    }
    __syncthreads();

    // ---- stage 1: scores ----
    {
        const int wid = t >> 5, lane = t & 31;
        const int h0 = lane * 8;
        float4 w0 = *reinterpret_cast<const float4*>(wh  + h0);
        float4 w1 = *reinterpret_cast<const float4*>(wh  + h0 + 4);
        float4 s0 = *reinterpret_cast<const float4*>(wsh + h0);
        float4 s1 = *reinterpret_cast<const float4*>(wsh + h0 + 4);
        float4 v0 = *reinterpret_cast<const float4*>(av  + h0);
        float4 v1 = *reinterpret_cast<const float4*>(av  + h0 + 4);
        for (int s = wid; s < SS; s += 32) {
            const float4* e = reinterpret_cast<const float4*>(enc + ((size_t)b * SS + s) * HH + h0);
            float4 e0 = e[0], e1 = e[1];
            float sum;
            sum  = v0.x * tanh_e(fmaf(w0.x, e0.x, s0.x));
            sum += v0.y * tanh_e(fmaf(w0.y, e0.y, s0.y));
            sum += v0.z * tanh_e(fmaf(w0.z, e0.z, s0.z));
            sum += v0.w * tanh_e(fmaf(w0.w, e0.w, s0.w));
            sum += v1.x * tanh_e(fmaf(w1.x, e1.x, s1.x));
            sum += v1.y * tanh_e(fmaf(w1.y, e1.y, s1.y));
            sum += v1.z * tanh_e(fmaf(w1.z, e1.z, s1.z));
            sum += v1.w * tanh_e(fmaf(w1.w, e1.w, s1.w));
#pragma unroll
            for (int o = 16; o; o >>= 1) sum += __shfl_xor_sync(0xffffffffu, sum, o);
            if (lane == 0) att[s] = sum;
        }
    }
    __syncthreads();

    // ---- stage 2: softmax over S ----
    float v = (t < SS) ? att[t] : -INFINITY;
    red[t] = v; __syncthreads();
#pragma unroll
    for (int o = 512; o; o >>= 1) { if (t < o) red[t] = fmaxf(red[t], red[t + o]); __syncthreads(); }
    float mx = red[0]; __syncthreads();
    float ev = (t < SS) ? __expf(v - mx) : 0.f;
    red[t] = ev; __syncthreads();
#pragma unroll
    for (int o = 512; o; o >>= 1) { if (t < o) red[t] += red[t + o]; __syncthreads(); }
    float inv = __fdividef(1.f, red[0]); __syncthreads();
    if (t < SS) {
        float a = ev * inv;
        att[t] = a;
        out_at[b * SS + t] = a;
    }
    __syncthreads();

    // ---- stage 3: context ----
    {
        int h = t & 255;
        int part = t >> 8;
        int sBeg = part * 100;
        const float* e = enc + (size_t)b * SS * HH + (size_t)sBeg * HH + h;
        float c = 0.f;
#pragma unroll 10
        for (int s = 0; s < 100; s++) c = fmaf(att[sBeg + s], e[(size_t)s * HH], c);
        red[t] = c;
    }
    __syncthreads();
    if (t < 512) red[t] += red[t + 512];
    __syncthreads();
    if (t < 256) ctx[t] = red[t] + red[t + 256];
    __syncthreads();

    // ---- stage 4: p_gen ----
    float pv = 0.f;
    if (t < 256)      pv = hnews[t] * __ldg(genw + t);
    else if (t < 512) pv = ctx[t - 256] * __ldg(genw + t);
    else if (t < 640) pv = emb[(size_t)tok[b] * EE + (t - 512)] * __ldg(genw + t);
    red[t] = pv; __syncthreads();
#pragma unroll
    for (int o = 512; o; o >>= 1) { if (t < o) red[t] += red[t + o]; __syncthreads(); }
    if (t == 0) {
        float p = sigm(red[0] + __ldg(genb));
        out_pg[b] = p;
        g_pgen[b] = p;
    }

    // ---- stage 5: hid = outh_b + outh_w @ [hnews|ctx] ----
    {
        int n = t >> 3;
        int kpart = t & 7;
        const float* dcsrc = (kpart < 4) ? (hnews + kpart * 64) : (ctx + (kpart - 4) * 64);
        const float* wrow = outhw + (size_t)n * 512 + kpart * 64;
        float s = 0.f;
#pragma unroll
        for (int i = 0; i < 64; i += 4) {
            float4 wv = *reinterpret_cast<const float4*>(wrow + i);
            s += wv.x * dcsrc[i]     + wv.y * dcsrc[i + 1]
               + wv.z * dcsrc[i + 2] + wv.w * dcsrc[i + 3];
        }
#pragma unroll
        for (int o = 4; o; o >>= 1) s += __shfl_xor_sync(0xffffffffu, s, o);
        if (kpart == 0) g_hid[b * EE + n] = s + __ldg(outhb + n);
    }
}

// ---------------- logits GEMM (256 thr, 8x4, proven) -> stores exp(v - tile_max) ----------------
__global__ __launch_bounds__(256, 2) void logits_kernel(
    const float* __restrict__ A, const float* __restrict__ W,
    const float* __restrict__ bias, float* __restrict__ E)
{
    __shared__ float2 As[8][132];
    __shared__ float2 Ws[8][68];

    const int tid = threadIdx.x;
    const int tx = tid & 15;
    const int ty = tid >> 4;
    const int n0 = blockIdx.x * 64;

    unsigned long long acc[8][4];
#pragma unroll
    for (int i = 0; i < 8; i++)
#pragma unroll
        for (int j = 0; j < 4; j++) acc[i][j] = 0ULL;

    for (int kt = 0; kt < EE; kt += 16) {
        __syncthreads();
#pragma unroll
        for (int t = 0; t < 4; t++) {
            int lin = tid + t * 256;
            int m = lin >> 3, kp = lin & 7;
            As[kp][m] = *reinterpret_cast<const float2*>(A + (size_t)m * EE + kt + 2 * kp);
        }
#pragma unroll
        for (int t = 0; t < 2; t++) {
            int lin = tid + t * 256;
            int nn = lin >> 3, kp = lin & 7;
            int row = n0 + nn;
            if (row >= VV) row = VV - 1;
            Ws[kp][nn] = *reinterpret_cast<const float2*>(W + (size_t)row * EE + kt + 2 * kp);
        }
        __syncthreads();

#pragma unroll
        for (int kp = 0; kp < 8; kp++) {
            unsigned long long a[8], w[4];
            const ulonglong2* ap = reinterpret_cast<const ulonglong2*>(&As[kp][ty * 8]);
            ulonglong2 q0 = ap[0], q1 = ap[1], q2 = ap[2], q3 = ap[3];
            a[0] = q0.x; a[1] = q0.y; a[2] = q1.x; a[3] = q1.y;
            a[4] = q2.x; a[5] = q2.y; a[6] = q3.x; a[7] = q3.y;
            const ulonglong2* wp = reinterpret_cast<const ulonglong2*>(&Ws[kp][tx * 4]);
            ulonglong2 r0 = wp[0], r1 = wp[1];
            w[0] = r0.x; w[1] = r0.y; w[2] = r1.x; w[3] = r1.y;
#pragma unroll
            for (int i = 0; i < 8; i++)
#pragma unroll
                for (int j = 0; j < 4; j++) fma2(acc[i][j], a[i], w[j]);
        }
    }

    // epilogue: bias, tile max, exp store, sum partials
#pragma unroll
    for (int i = 0; i < 8; i++) {
        int m = ty * 8 + i;
        float vls[4];
        float mloc = -INFINITY;
#pragma unroll
        for (int j = 0; j < 4; j++) {
            int n = n0 + tx * 4 + j;
            bool valid = n < VV;
            int nc = valid ? n : VV - 1;
            float c = unpack_sum(acc[i][j]) + __ldg(bias + nc);
            vls[j] = valid ? c : -INFINITY;
            if (valid) mloc = fmaxf(mloc, c);
        }
#pragma unroll
        for (int o = 8; o; o >>= 1) mloc = fmaxf(mloc, __shfl_xor_sync(0xffffffffu, mloc, o));
        float s = 0.f;
#pragma unroll
        for (int j = 0; j < 4; j++) {
            int n = n0 + tx * 4 + j;
            if (n < VV) {
                float e = __expf(vls[j] - mloc);
                E[(size_t)m * VV + n] = e;
                s += e;
            }
        }
#pragma unroll
        for (int o = 8; o; o >>= 1) s += __shfl_xor_sync(0xffffffffu, s, o);
        if (tx == 0) {
            g_tmax[m * TSTRIDE + blockIdx.x] = mloc;
            g_tsum[m * TSTRIDE + blockIdx.x] = s;
        }
    }
}

// ---------------- merge partials: per-row max + inverse sum ----------------
__global__ void merge_kernel()
{
    int b = blockIdx.x, t = threadIdx.x;   // 128 threads
    __shared__ float red[128];
    float mx = -INFINITY;
    for (int i = t; i < NTILES_L; i += 128) mx = fmaxf(mx, g_tmax[b * TSTRIDE + i]);
    red[t] = mx; __syncthreads();
#pragma unroll
    for (int o = 64; o; o >>= 1) { if (t < o) red[t] = fmaxf(red[t], red[t + o]); __syncthreads(); }
    mx = red[0]; __syncthreads();
    float s = 0.f;
    for (int i = t; i < NTILES_L; i += 128)
        s += g_tsum[b * TSTRIDE + i] * __expf(g_tmax[b * TSTRIDE + i] - mx);
    red[t] = s; __syncthreads();
#pragma unroll
    for (int o = 64; o; o >>= 1) { if (t < o) red[t] += red[t + o]; __syncthreads(); }
    if (t == 0) { g_rowmax[b] = mx; g_rowinv[b] = __fdividef(1.f, red[0]); }
}

// ---------------- finalize: scale precomputed exps, vectorized ----------------
// grid (25, 128), 256 thr; chunk 2048 elems = 32 tiles of 64
__global__ __launch_bounds__(256) void finalize_kernel(float* __restrict__ out_pv, float* __restrict__ out_pf)
{
    const int b = blockIdx.y, t = threadIdx.x;
    const int start = blockIdx.x * 2048;
    __shared__ float sc[32];

    if (t < 32) {
        int tile = (start >> 6) + t;
        float s = 0.f;
        if (tile < NTILES_L)
            s = __expf(g_tmax[b * TSTRIDE + tile] - g_rowmax[b]) * g_rowinv[b];
        sc[t] = s;
    }
    __syncthreads();

    const float pg = g_pgen[b];
    const float* ev = g_expv + (size_t)b * VV + start;
    float* pv = out_pv + (size_t)b * VV + start;
    float* pf = out_pf + (size_t)b * VP + start;

#pragma unroll
    for (int k = 0; k < 2; k++) {
        int e4 = t + k * 256;               // float4 index within chunk
        int i = e4 * 4;
        if (start + i < VV) {
            float s = sc[i >> 6];
            float4 x = *reinterpret_cast<const float4*>(ev + i);
            float4 p;
            p.x = x.x * s; p.y = x.y * s; p.z = x.z * s; p.w = x.w * s;
            *reinterpret_cast<float4*>(pv + i) = p;
            float2 f0 = make_float2(p.x * pg, p.y * pg);
            float2 f1 = make_float2(p.z * pg, p.w * pg);
            *reinterpret_cast<float2*>(pf + i)     = f0;
            *reinterpret_cast<float2*>(pf + i + 2) = f1;
        }
    }
    if (blockIdx.x == 0 && t < PADV) out_pf[(size_t)b * VP + VV + t] = 0.f;
}

// ---------------- copy-mechanism scatter ----------------
__global__ void scatter_kernel(const int* __restrict__ fiv, const float* __restrict__ att,
                               float* __restrict__ out_pf)
{
    int b = blockIdx.x, s = threadIdx.x;
    if (s < SS) {
        float w = (1.f - g_pgen[b]) * att[b * SS + s];
        atomicAdd(&out_pf[(size_t)b * VP + fiv[b * SS + s]], w);
    }
}

// ---------------- launch ----------------
extern "C" void kernel_launch(void* const* d_in, const int* in_sizes, int n_in,
                              void* d_out, int out_size)
{
    const int*   tok   = (const int*)d_in[0];
    const float* hprev = (const float*)d_in[1];
    const float* enc   = (const float*)d_in[2];
    const int*   fiv   = (const int*)d_in[3];
    const float* emb   = (const float*)d_in[4];
    const float* w_ih  = (const float*)d_in[5];
    const float* w_hh  = (const float*)d_in[6];
    const float* b_ih  = (const float*)d_in[7];
    const float* b_hh  = (const float*)d_in[8];
    const float* w_h   = (const float*)d_in[9];
    const float* w_s   = (const float*)d_in[10];
    const float* attb  = (const float*)d_in[11];
    const float* attv  = (const float*)d_in[12];
    const float* genw  = (const float*)d_in[13];
    const float* genb  = (const float*)d_in[14];
    const float* outhw = (const float*)d_in[15];
    const float* outhb = (const float*)d_in[16];
    const float* outvw = (const float*)d_in[17];
    const float* outvb = (const float*)d_in[18];

    float* out    = (float*)d_out;
    float* out_h  = out;
    float* out_pf = out + 32768;
    float* out_pg = out + 6464768;
    float* out_pv = out + 6464896;
    float* out_at = out + 12864896;

    float *p_hid, *p_expv;
    cudaGetSymbolAddress((void**)&p_hid,  g_hid);
    cudaGetSymbolAddress((void**)&p_expv, g_expv);

    gates_gemm<<<dim3(12, 12), 256>>>(emb, tok, w_ih, hprev, w_hh);

    attn_fused<<<128, 1024>>>(enc, emb, tok, hprev, b_ih, b_hh, w_s, attb,
                              w_h, attv, genw, genb, outhw, outhb,
                              out_h, out_at, out_pg);

    logits_kernel<<<NTILES_L, 256>>>(p_hid, outvw, outvb, p_expv);

    merge_kernel<<<128, 128>>>();

    finalize_kernel<<<dim3(25, 128), 256>>>(out_pv, out_pf);
    scatter_kernel<<<128, 512>>>(fiv, out_at, out_pf);
}